// round 2
// baseline (speedup 1.0000x reference)
#include <cuda_runtime.h>
#include <cuda_fp16.h>
#include <mma.h>

using namespace nvcuda;

#define BB 256
#define TT 512
#define II 256
#define HH 512
#define G4 2048            // 4H
#define K0 (II + HH)       // 768
#define K1 (HH + HH)       // 1024
#define NBLK 128
#define NTHR 256
#define KC 64
#define LDA 80             // halves (160B, 32B-aligned rows)
#define LDB 144            // halves (288B)
#define LDC 136            // floats (544B)
#define SMEM_BYTES 34816   // max(64*LDA*2 + 64*LDB*2 = 28672, 64*LDC*4 = 34816)

// ---------------- device global scratch (no allocs allowed) ----------------
__device__ __half g_Xh[(size_t)TT * BB * II];     // [T][B][I] fp16
__device__ __half g_W0[(size_t)K0 * G4];          // [768][2048] gate-interleaved
__device__ __half g_W1[(size_t)K1 * G4];          // [1024][2048]
__device__ float  g_bias0[G4];
__device__ float  g_bias1[G4];
__device__ __half g_h0[2][BB * HH];
__device__ __half g_h1[2][BB * HH];
__device__ float  g_c0[BB * HH];
__device__ float  g_c1[BB * HH];
__device__ unsigned long long g_count = 0;
__device__ volatile unsigned long long g_epoch = 0;

// ---------------- grid barrier (sense-epoch, replay-safe) ----------------
__device__ __forceinline__ void grid_barrier() {
    __syncthreads();
    if (threadIdx.x == 0) {
        __threadfence();
        unsigned long long e = g_epoch;
        if (atomicAdd(&g_count, 1ULL) == (unsigned long long)(NBLK - 1)) {
            g_count = 0;
            __threadfence();
            g_epoch = e + 1;
        } else {
            while (g_epoch == e) { __nanosleep(32); }
        }
    }
    __syncthreads();
}

__device__ __forceinline__ float sigmoidf_(float x) {
    return 1.0f / (1.0f + __expf(-x));
}

// One [64 x 128] output tile of C = A[256,K] @ W[K,2048] (+bias), then fused
// LSTM elementwise update writing h (fp16) and c (fp32).
// A is split: k < split from pA1 (row stride ld1), else pA2 (row stride HH).
__device__ void do_tile(unsigned char* smem_raw,
                        const __half* __restrict__ pA1, int ld1, int split,
                        const __half* __restrict__ pA2,
                        const __half* __restrict__ W, int Ktot,
                        const float* __restrict__ bias,
                        float* __restrict__ cbuf, __half* __restrict__ hout,
                        int m0, int n0)
{
    __half* sA = (__half*)smem_raw;
    __half* sB = (__half*)(smem_raw + 64 * LDA * 2);
    float*  sC = (float*)smem_raw;

    const int warp = threadIdx.x >> 5;
    const int wm = warp >> 2;   // 0..1  (32-row slab)
    const int wn = warp & 3;    // 0..3  (32-col slab)

    wmma::fragment<wmma::accumulator, 16, 16, 16, float> cf[2][2];
#pragma unroll
    for (int i = 0; i < 2; ++i)
#pragma unroll
        for (int j = 0; j < 2; ++j)
            wmma::fill_fragment(cf[i][j], 0.0f);

    for (int kc = 0; kc < Ktot; kc += KC) {
        // --- load A chunk: 64 rows x 64 halves (L2-coherent: state changes) ---
        for (int idx = threadIdx.x; idx < 64 * 8; idx += NTHR) {
            int r  = idx >> 3;
            int k8 = (idx & 7) << 3;
            int kg = kc + k8;
            const __half* src;
            int ld;
            if (kg < split) { src = pA1; ld = ld1; }
            else            { src = pA2; ld = HH; kg -= split; }
            uint4 v = __ldcg((const uint4*)(src + (size_t)(m0 + r) * ld + kg));
            *(uint4*)(sA + r * LDA + k8) = v;
        }
        // --- load B chunk: 64 k-rows x 128 cols (weights: L1-cacheable) ---
        for (int idx = threadIdx.x; idx < 64 * 16; idx += NTHR) {
            int r  = idx >> 4;
            int n8 = (idx & 15) << 3;
            uint4 v = *(const uint4*)(W + (size_t)(kc + r) * G4 + n0 + n8);
            *(uint4*)(sB + r * LDB + n8) = v;
        }
        __syncthreads();

#pragma unroll
        for (int ks = 0; ks < KC; ks += 16) {
            wmma::fragment<wmma::matrix_a, 16, 16, 16, __half, wmma::row_major> af[2];
            wmma::fragment<wmma::matrix_b, 16, 16, 16, __half, wmma::row_major> bf[2];
#pragma unroll
            for (int i = 0; i < 2; ++i)
                wmma::load_matrix_sync(af[i], sA + (wm * 32 + i * 16) * LDA + ks, LDA);
#pragma unroll
            for (int j = 0; j < 2; ++j)
                wmma::load_matrix_sync(bf[j], sB + ks * LDB + wn * 32 + j * 16, LDB);
#pragma unroll
            for (int i = 0; i < 2; ++i)
#pragma unroll
                for (int j = 0; j < 2; ++j)
                    wmma::mma_sync(cf[i][j], af[i], bf[j], cf[i][j]);
        }
        __syncthreads();
    }

    // --- store accumulators to smem for gate-grouped elementwise ---
#pragma unroll
    for (int i = 0; i < 2; ++i)
#pragma unroll
        for (int j = 0; j < 2; ++j)
            wmma::store_matrix_sync(sC + (wm * 32 + i * 16) * LDC + (wn * 32 + j * 16),
                                    cf[i][j], LDC, wmma::mem_row_major);
    __syncthreads();

    // --- fused LSTM cell update: cols 4j..4j+3 = (i,f,g,o) of hidden unit j ---
    for (int idx = threadIdx.x; idx < 64 * 32; idx += NTHR) {
        int r = idx >> 5;
        int j = idx & 31;
        int b  = m0 + r;
        int jg = (n0 >> 2) + j;
        float4 gv = *(float4*)(sC + r * LDC + 4 * j);
        float4 bv = *(const float4*)(bias + n0 + 4 * j);
        float iv = sigmoidf_(gv.x + bv.x);
        float fv = sigmoidf_(gv.y + bv.y);
        float gg = tanhf(gv.z + bv.z);
        float ov = sigmoidf_(gv.w + bv.w);
        float c  = fv * cbuf[b * HH + jg] + iv * gg;
        cbuf[b * HH + jg] = c;
        hout[b * HH + jg] = __float2half(ov * tanhf(c));
    }
}

__global__ void __launch_bounds__(NTHR, 1)
lstm_kernel(const float* __restrict__ X,
            const float* __restrict__ Wih0, const float* __restrict__ Whh0,
            const float* __restrict__ bih0, const float* __restrict__ bhh0,
            const float* __restrict__ Wih1, const float* __restrict__ Whh1,
            const float* __restrict__ bih1, const float* __restrict__ bhh1,
            const float* __restrict__ Wlin, const float* __restrict__ blin,
            float* __restrict__ out)
{
    __shared__ __align__(128) unsigned char smem_raw[SMEM_BYTES];

    const int gtid = blockIdx.x * NTHR + threadIdx.x;
    const int gstride = NBLK * NTHR;

    // ---------- prologue: layout conversion (re-done every launch) ----------
    // X [B][T][I] fp32 -> g_Xh [T][B][I] fp16
    for (int i = gtid; i < BB * TT * II; i += gstride) {
        int b  = i >> 17;          // /(T*I)
        int rem = i & 131071;
        int t  = rem >> 8;         // /I
        int ii = rem & 255;
        g_Xh[((size_t)t * BB + b) * II + ii] = __float2half(X[i]);
    }
    // W_ih0 [2048][256] -> g_W0 rows [0,256), gate-interleaved cols
    for (int i = gtid; i < G4 * II; i += gstride) {
        int r = i >> 8, k = i & 255;
        int n = ((r & 511) << 2) | (r >> 9);
        g_W0[(size_t)k * G4 + n] = __float2half(Wih0[i]);
    }
    // W_hh0 [2048][512] -> g_W0 rows [256,768)
    for (int i = gtid; i < G4 * HH; i += gstride) {
        int r = i >> 9, k = i & 511;
        int n = ((r & 511) << 2) | (r >> 9);
        g_W0[(size_t)(II + k) * G4 + n] = __float2half(Whh0[i]);
    }
    // W_ih1 [2048][512] -> g_W1 rows [0,512)
    for (int i = gtid; i < G4 * HH; i += gstride) {
        int r = i >> 9, k = i & 511;
        int n = ((r & 511) << 2) | (r >> 9);
        g_W1[(size_t)k * G4 + n] = __float2half(Wih1[i]);
    }
    // W_hh1 [2048][512] -> g_W1 rows [512,1024)
    for (int i = gtid; i < G4 * HH; i += gstride) {
        int r = i >> 9, k = i & 511;
        int n = ((r & 511) << 2) | (r >> 9);
        g_W1[(size_t)(HH + k) * G4 + n] = __float2half(Whh1[i]);
    }
    // biases (fused b_ih + b_hh), permuted
    for (int i = gtid; i < G4; i += gstride) {
        int n = ((i & 511) << 2) | (i >> 9);
        g_bias0[n] = bih0[i] + bhh0[i];
        g_bias1[n] = bih1[i] + bhh1[i];
    }
    // zero state
    for (int i = gtid; i < BB * HH; i += gstride) {
        g_c0[i] = 0.0f; g_c1[i] = 0.0f;
        __half z = __float2half(0.0f);
        g_h0[0][i] = z; g_h0[1][i] = z;
        g_h1[0][i] = z; g_h1[1][i] = z;
    }
    grid_barrier();

    // ---------- main skewed recurrence ----------
    const int tile = blockIdx.x & 63;
    const int m0 = (tile >> 4) * 64;     // 4 M-groups
    const int n0 = (tile & 15) * 128;    // 16 N-groups
    const bool is_l1 = (blockIdx.x >= 64);

    for (int it = 0; it <= TT; ++it) {
        const int rd = it & 1;
        const int wr = rd ^ 1;
        if (!is_l1) {
            if (it < TT) {
                // layer0 step t=it: A = [x_t | h0_prev], out h0[wr]
                do_tile(smem_raw,
                        g_Xh + (size_t)it * BB * II, II, II,
                        g_h0[rd],
                        g_W0, K0, g_bias0,
                        g_c0, g_h0[wr], m0, n0);
            }
        } else {
            if (it >= 1) {
                // layer1 step t=it-1: A = [h0(t) | h1_prev], out h1[wr]
                do_tile(smem_raw,
                        g_h0[rd], HH, HH,
                        g_h1[rd],
                        g_W1, K1, g_bias1,
                        g_c1, g_h1[wr], m0, n0);
            }
        }
        grid_barrier();
    }

    // ---------- head: y = h1(T-1) @ W_lin^T + b_lin ----------
    // h1(T-1) written at it=T into parity (T+1)&1 = 1.
    if (blockIdx.x == 0) {
        for (int b = threadIdx.x; b < BB; b += NTHR) {
            float acc = blin[0];
            for (int k = 0; k < HH; k += 8) {
                uint4 v = __ldcg((const uint4*)(&g_h1[1][b * HH + k]));
                const __half* hv = (const __half*)&v;
#pragma unroll
                for (int u = 0; u < 8; ++u)
                    acc += __half2float(hv[u]) * Wlin[k + u];
            }
            out[b] = acc;
        }
    }
}

extern "C" void kernel_launch(void* const* d_in, const int* in_sizes, int n_in,
                              void* d_out, int out_size) {
    (void)in_sizes; (void)n_in; (void)out_size;
    lstm_kernel<<<NBLK, NTHR>>>(
        (const float*)d_in[0],
        (const float*)d_in[1], (const float*)d_in[2],
        (const float*)d_in[3], (const float*)d_in[4],
        (const float*)d_in[5], (const float*)d_in[6],
        (const float*)d_in[7], (const float*)d_in[8],
        (const float*)d_in[9], (const float*)d_in[10],
        (float*)d_out);
}

// round 3
// speedup vs baseline: 2.5463x; 2.5463x over previous
#include <cuda_runtime.h>
#include <cuda_fp16.h>
#include <mma.h>

using namespace nvcuda;

#define BB 256
#define TT 512
#define II 256
#define HH 512
#define G4 2048            // 4H
#define K0 (II + HH)       // 768
#define K1 (HH + HH)       // 1024
#define NBLK 128
#define NTHR 256
#define KC 64
#define LDA 72             // halves (144B rows, 16B aligned)
#define LDB 136            // halves (272B rows, 16B aligned)
#define LDC 136            // floats
#define A_BYTES (64 * LDA * 2)                 // 9216
#define STAGE_BYTES (A_BYTES + 64 * LDB * 2)   // 26624
#define SMEM_DYN (2 * STAGE_BYTES)             // 53248 (sC 34816 aliases)

// ---------------- device global scratch ----------------
__device__ __half g_Xh[(size_t)TT * BB * II];     // [T][B][I] fp16
__device__ __half g_W0[(size_t)K0 * G4];          // gate-interleaved
__device__ __half g_W1[(size_t)K1 * G4];
__device__ float  g_bias0[G4];
__device__ float  g_bias1[G4];
__device__ __half g_h0[2][BB * HH];
__device__ __half g_h1[2][BB * HH];
__device__ unsigned long long g_count = 0;
__device__ volatile unsigned long long g_epoch = 0;

// ---------------- grid barrier (sense-epoch, replay-safe) ----------------
__device__ __forceinline__ void grid_barrier() {
    __syncthreads();
    if (threadIdx.x == 0) {
        __threadfence();
        unsigned long long e = g_epoch;
        if (atomicAdd(&g_count, 1ULL) == (unsigned long long)(NBLK - 1)) {
            g_count = 0;
            __threadfence();
            g_epoch = e + 1;
        } else {
            while (g_epoch == e) { __nanosleep(32); }
        }
    }
    __syncthreads();
}

__device__ __forceinline__ float sigmoidf_(float x) {
    return 1.0f / (1.0f + __expf(-x));
}

// ---------------- cp.async helpers (L1-bypassing, L2-coherent) ----------------
__device__ __forceinline__ void cp_async16(void* smem, const void* g) {
    unsigned saddr = (unsigned)__cvta_generic_to_shared(smem);
    asm volatile("cp.async.cg.shared.global [%0], [%1], 16;" :: "r"(saddr), "l"(g));
}
__device__ __forceinline__ void cp_commit() {
    asm volatile("cp.async.commit_group;");
}
template <int N> __device__ __forceinline__ void cp_wait() {
    asm volatile("cp.async.wait_group %0;" :: "n"(N));
}

// Load one K-chunk (A: 64xKC, B: KCx128) into a stage via cp.async.
__device__ __forceinline__ void load_chunk(char* stage,
                                           const __half* __restrict__ Abase, int lda,
                                           const __half* __restrict__ W, int kc, int n0)
{
    __half* sA = (__half*)stage;
    __half* sB = (__half*)(stage + A_BYTES);
    const int t = threadIdx.x;
#pragma unroll
    for (int i = 0; i < 2; ++i) {            // 512 x 16B for A
        int idx = t + i * NTHR;
        int r = idx >> 3, c = (idx & 7) << 3;
        cp_async16(sA + r * LDA + c, Abase + (size_t)r * lda + c);
    }
#pragma unroll
    for (int i = 0; i < 4; ++i) {            // 1024 x 16B for B
        int idx = t + i * NTHR;
        int r = idx >> 4, c = (idx & 15) << 3;
        cp_async16(sB + r * LDB + c, W + (size_t)(kc + r) * G4 + n0 + c);
    }
}

// One [64 x 128] tile of C = A[.,K] @ W[K,2048] (+bias), fused LSTM update.
// c state lives in c_reg[8] (fixed thread mapping). Chunk k-source: k<split
// from pA1 (stride ld1) else pA2 (stride HH); split is a KC multiple.
__device__ void do_tile(char* smem,
                        const __half* __restrict__ pA1, int ld1, int split,
                        const __half* __restrict__ pA2,
                        const __half* __restrict__ W, int Ktot,
                        const float* __restrict__ bias,
                        float* c_reg, __half* __restrict__ hout,
                        int m0, int n0)
{
    const int warp = threadIdx.x >> 5;
    const int wm = warp >> 2;   // 0..1
    const int wn = warp & 3;    // 0..3

    wmma::fragment<wmma::accumulator, 16, 16, 16, float> cf[2][2];
#pragma unroll
    for (int i = 0; i < 2; ++i)
#pragma unroll
        for (int j = 0; j < 2; ++j)
            wmma::fill_fragment(cf[i][j], 0.0f);

    const int nch = Ktot / KC;

    // preload chunk 0 into stage 0
    {
        const __half* Ab = pA1 + (size_t)m0 * ld1;   // kc=0 < split always
        load_chunk(smem, Ab, ld1, W, 0, n0);
        cp_commit();
    }

    for (int c = 0; c < nch; ++c) {
        if (c + 1 < nch) {
            int kc = (c + 1) * KC;
            const __half* Ab; int lda;
            if (kc < split) { Ab = pA1 + (size_t)m0 * ld1 + kc; lda = ld1; }
            else            { Ab = pA2 + (size_t)m0 * HH + (kc - split); lda = HH; }
            load_chunk(smem + ((c + 1) & 1) * STAGE_BYTES, Ab, lda, W, kc, n0);
            cp_commit();
            cp_wait<1>();
        } else {
            cp_wait<0>();
        }
        __syncthreads();

        char* st = smem + (c & 1) * STAGE_BYTES;
        __half* sA = (__half*)st;
        __half* sB = (__half*)(st + A_BYTES);
#pragma unroll
        for (int ks = 0; ks < KC; ks += 16) {
            wmma::fragment<wmma::matrix_a, 16, 16, 16, __half, wmma::row_major> af[2];
            wmma::fragment<wmma::matrix_b, 16, 16, 16, __half, wmma::row_major> bf[2];
#pragma unroll
            for (int i = 0; i < 2; ++i)
                wmma::load_matrix_sync(af[i], sA + (wm * 32 + i * 16) * LDA + ks, LDA);
#pragma unroll
            for (int j = 0; j < 2; ++j)
                wmma::load_matrix_sync(bf[j], sB + ks * LDB + wn * 32 + j * 16, LDB);
#pragma unroll
            for (int i = 0; i < 2; ++i)
#pragma unroll
                for (int j = 0; j < 2; ++j)
                    wmma::mma_sync(cf[i][j], af[i], bf[j], cf[i][j]);
        }
        __syncthreads();
    }

    // accumulators -> smem for gate-grouped elementwise
    float* sC = (float*)smem;
#pragma unroll
    for (int i = 0; i < 2; ++i)
#pragma unroll
        for (int j = 0; j < 2; ++j)
            wmma::store_matrix_sync(sC + (wm * 32 + i * 16) * LDC + (wn * 32 + j * 16),
                                    cf[i][j], LDC, wmma::mem_row_major);
    __syncthreads();

    // fused LSTM cell: cols 4j..4j+3 = (i,f,g,o) of hidden unit j
#pragma unroll
    for (int k = 0; k < 8; ++k) {
        int idx = threadIdx.x + k * NTHR;  // 0..2047
        int r = idx >> 5;
        int j = idx & 31;
        int b  = m0 + r;
        int jg = (n0 >> 2) + j;
        float4 gv = *(float4*)(sC + r * LDC + 4 * j);
        float4 bv = *(const float4*)(bias + n0 + 4 * j);
        float iv = sigmoidf_(gv.x + bv.x);
        float fv = sigmoidf_(gv.y + bv.y);
        float gg = tanhf(gv.z + bv.z);
        float ov = sigmoidf_(gv.w + bv.w);
        float cc = fv * c_reg[k] + iv * gg;
        c_reg[k] = cc;
        hout[b * HH + jg] = __float2half(ov * tanhf(cc));
    }
    // grid_barrier (caller) protects sC before next iteration's preload
}

__global__ void __launch_bounds__(NTHR, 1)
lstm_kernel(const float* __restrict__ X,
            const float* __restrict__ Wih0, const float* __restrict__ Whh0,
            const float* __restrict__ bih0, const float* __restrict__ bhh0,
            const float* __restrict__ Wih1, const float* __restrict__ Whh1,
            const float* __restrict__ bih1, const float* __restrict__ bhh1,
            const float* __restrict__ Wlin, const float* __restrict__ blin,
            float* __restrict__ out)
{
    extern __shared__ __align__(128) char smem[];

    const int gtid = blockIdx.x * NTHR + threadIdx.x;
    const int gstride = NBLK * NTHR;

    // ---------- prologue: layout conversion ----------
    for (int i = gtid; i < BB * TT * II; i += gstride) {
        int b  = i >> 17;
        int rem = i & 131071;
        int t  = rem >> 8;
        int ii = rem & 255;
        g_Xh[((size_t)t * BB + b) * II + ii] = __float2half(X[i]);
    }
    for (int i = gtid; i < G4 * II; i += gstride) {
        int r = i >> 8, k = i & 255;
        int n = ((r & 511) << 2) | (r >> 9);
        g_W0[(size_t)k * G4 + n] = __float2half(Wih0[i]);
    }
    for (int i = gtid; i < G4 * HH; i += gstride) {
        int r = i >> 9, k = i & 511;
        int n = ((r & 511) << 2) | (r >> 9);
        g_W0[(size_t)(II + k) * G4 + n] = __float2half(Whh0[i]);
    }
    for (int i = gtid; i < G4 * HH; i += gstride) {
        int r = i >> 9, k = i & 511;
        int n = ((r & 511) << 2) | (r >> 9);
        g_W1[(size_t)k * G4 + n] = __float2half(Wih1[i]);
    }
    for (int i = gtid; i < G4 * HH; i += gstride) {
        int r = i >> 9, k = i & 511;
        int n = ((r & 511) << 2) | (r >> 9);
        g_W1[(size_t)(HH + k) * G4 + n] = __float2half(Whh1[i]);
    }
    for (int i = gtid; i < G4; i += gstride) {
        int n = ((i & 511) << 2) | (i >> 9);
        g_bias0[n] = bih0[i] + bhh0[i];
        g_bias1[n] = bih1[i] + bhh1[i];
    }
    for (int i = gtid; i < BB * HH; i += gstride) {
        __half z = __float2half(0.0f);
        g_h0[0][i] = z; g_h0[1][i] = z;
        g_h1[0][i] = z; g_h1[1][i] = z;
    }
    grid_barrier();

    // ---------- main skewed recurrence ----------
    const int tile = blockIdx.x & 63;
    const int m0 = (tile >> 4) * 64;     // 4 M-groups
    const int n0 = (tile & 15) * 128;    // 16 N-groups
    const bool is_l1 = (blockIdx.x >= 64);

    float c_reg[8];
#pragma unroll
    for (int k = 0; k < 8; ++k) c_reg[k] = 0.0f;

    for (int it = 0; it <= TT; ++it) {
        const int rd = it & 1;
        const int wr = rd ^ 1;
        if (!is_l1) {
            if (it < TT) {
                do_tile(smem,
                        g_Xh + (size_t)it * BB * II, II, II,
                        g_h0[rd],
                        g_W0, K0, g_bias0,
                        c_reg, g_h0[wr], m0, n0);
            }
        } else {
            if (it >= 1) {
                do_tile(smem,
                        g_h0[rd], HH, HH,
                        g_h1[rd],
                        g_W1, K1, g_bias1,
                        c_reg, g_h1[wr], m0, n0);
            }
        }
        grid_barrier();
    }

    // ---------- head: y = h1(T-1) @ W_lin^T + b_lin ----------
    if (blockIdx.x == 0) {
        for (int b = threadIdx.x; b < BB; b += NTHR) {
            float acc = blin[0];
            for (int k = 0; k < HH; k += 8) {
                uint4 v = __ldcg((const uint4*)(&g_h1[1][b * HH + k]));
                const __half* hv = (const __half*)&v;
#pragma unroll
                for (int u = 0; u < 8; ++u)
                    acc += __half2float(hv[u]) * Wlin[k + u];
            }
            out[b] = acc;
        }
    }
}

extern "C" void kernel_launch(void* const* d_in, const int* in_sizes, int n_in,
                              void* d_out, int out_size) {
    (void)in_sizes; (void)n_in; (void)out_size;
    cudaFuncSetAttribute(lstm_kernel,
                         cudaFuncAttributeMaxDynamicSharedMemorySize, SMEM_DYN);
    lstm_kernel<<<NBLK, NTHR, SMEM_DYN>>>(
        (const float*)d_in[0],
        (const float*)d_in[1], (const float*)d_in[2],
        (const float*)d_in[3], (const float*)d_in[4],
        (const float*)d_in[5], (const float*)d_in[6],
        (const float*)d_in[7], (const float*)d_in[8],
        (const float*)d_in[9], (const float*)d_in[10],
        (float*)d_out);
}

// round 5
// speedup vs baseline: 2.7541x; 1.0816x over previous
#include <cuda_runtime.h>
#include <cuda_fp16.h>
#include <mma.h>
#include <cstdint>

using namespace nvcuda;

#define BB 256
#define TT 512
#define II 256
#define HH 512
#define G4 2048
#define K0 768
#define K1 1024
#define KC 128
#define NBLK 128
#define NTHR 256
#define LDA 136            // halves (272B rows)
#define LDB 136            // halves
#define LDC 136            // floats
#define A_BYTES (64 * LDA * 2)                    // 17408
#define B_BYTES (KC * LDB * 2)                    // 34816
#define STAGE_BYTES (A_BYTES + B_BYTES)           // 52224
#define SMEM_DYN (2 * STAGE_BYTES)                // 104448

// ---------------- device global scratch ----------------
__device__ __half g_Xh[(size_t)TT * BB * II];            // [T][B][I]
__device__ __half g_W0[(size_t)K0 * G4];                 // rows [W_ih0; W_hh0], gate-interleaved cols
__device__ __half g_W1[(size_t)K1 * G4];                 // rows [W_hh1; W_ih1]
__device__ float  g_bias0[G4];
__device__ float  g_bias1[G4];
__device__ __half g_h0[(size_t)(TT + 1) * BB * HH];      // full history, slot t+1 = output of step t
__device__ __half g_h1[(size_t)(TT + 1) * BB * HH];
__device__ int    g_flag0[(TT + 1) * 4];                 // [slot][slab], count to 16
__device__ int    g_flag1[(TT + 1) * 4];
__device__ unsigned long long g_count = 0;
__device__ volatile unsigned long long g_epoch = 0;

// ---------------- one-shot grid barrier (after prologue) ----------------
__device__ __forceinline__ void grid_barrier() {
    __syncthreads();
    if (threadIdx.x == 0) {
        __threadfence();
        unsigned long long e = g_epoch;
        if (atomicAdd(&g_count, 1ULL) == (unsigned long long)(NBLK - 1)) {
            g_count = 0;
            __threadfence();
            g_epoch = e + 1;
        } else {
            while (g_epoch == e) { __nanosleep(64); }
        }
    }
    __syncthreads();
}

__device__ __forceinline__ float sig_(float x) {
    return __fdividef(1.0f, 1.0f + __expf(-x));
}
__device__ __forceinline__ float tanh_(float x) {
    return __fmaf_rn(2.0f, sig_(2.0f * x), -1.0f);
}

// ---------------- cp.async helpers ----------------
__device__ __forceinline__ void cp_async16(void* smem, const void* g) {
    unsigned s = (unsigned)__cvta_generic_to_shared(smem);
    asm volatile("cp.async.cg.shared.global [%0], [%1], 16;" :: "r"(s), "l"(g));
}
__device__ __forceinline__ void cp_commit() { asm volatile("cp.async.commit_group;"); }
template <int N> __device__ __forceinline__ void cp_wait() {
    asm volatile("cp.async.wait_group %0;" :: "n"(N));
}

// ---------------- flag sync ----------------
__device__ __forceinline__ void poll_flag(const int* f) {
    int v = __ldcg(f);
    if (v < 16) {
        do { __nanosleep(64); v = __ldcg(f); } while (v < 16);
    }
    __threadfence();   // acquire: order subsequent reads after flag observation
}
__device__ __forceinline__ void release_flag(int* f) {
    __threadfence();
    atomicAdd(f, 1);
}

// load one chunk: A 64x128 halves, B 128x128 halves
__device__ __forceinline__ void load_chunk(char* stage,
                                           const __half* __restrict__ Abase, int lda,
                                           const __half* __restrict__ Bbase)
{
    __half* sA = (__half*)stage;
    __half* sB = (__half*)(stage + A_BYTES);
    const int t = threadIdx.x;
#pragma unroll
    for (int i = 0; i < 4; ++i) {            // 1024 x 16B for A
        int idx = t + i * NTHR;
        int r = idx >> 4, u = (idx & 15) << 3;
        cp_async16(sA + r * LDA + u, Abase + (size_t)r * lda + u);
    }
#pragma unroll
    for (int i = 0; i < 8; ++i) {            // 2048 x 16B for B
        int idx = t + i * NTHR;
        int r = idx >> 4, u = (idx & 15) << 3;
        cp_async16(sB + r * LDB + u, Bbase + (size_t)r * G4 + u);
    }
}

__global__ void __launch_bounds__(NTHR, 1)
lstm_kernel(const float* __restrict__ X,
            const float* __restrict__ Wih0, const float* __restrict__ Whh0,
            const float* __restrict__ bih0, const float* __restrict__ bhh0,
            const float* __restrict__ Wih1, const float* __restrict__ Whh1,
            const float* __restrict__ bih1, const float* __restrict__ bhh1,
            const float* __restrict__ Wlin, const float* __restrict__ blin,
            float* __restrict__ out)
{
    extern __shared__ __align__(128) char smem[];

    const int tid = threadIdx.x;
    const int gtid = blockIdx.x * NTHR + tid;
    const int gstride = NBLK * NTHR;

    // ---------------- prologue ----------------
    // X [B][T][I] fp32 -> g_Xh [T][B][I] fp16
    for (int i = gtid; i < BB * TT * II; i += gstride) {
        int b = i >> 17;
        int rem = i & 131071;
        int t = rem >> 8;
        int ii = rem & 255;
        g_Xh[((size_t)t * BB + b) * II + ii] = __float2half(X[i]);
    }
    // gate-interleave: output col n = ((r&511)<<2) | (r>>9)  (r = original gate row)
    for (int i = gtid; i < G4 * II; i += gstride) {          // W_ih0 -> rows 0..255
        int r = i >> 8, k = i & 255;
        int n = ((r & 511) << 2) | (r >> 9);
        g_W0[(size_t)k * G4 + n] = __float2half(Wih0[i]);
    }
    for (int i = gtid; i < G4 * HH; i += gstride) {          // W_hh0 -> rows 256..767
        int r = i >> 9, k = i & 511;
        int n = ((r & 511) << 2) | (r >> 9);
        g_W0[(size_t)(II + k) * G4 + n] = __float2half(Whh0[i]);
    }
    for (int i = gtid; i < G4 * HH; i += gstride) {          // W_hh1 -> rows 0..511
        int r = i >> 9, k = i & 511;
        int n = ((r & 511) << 2) | (r >> 9);
        g_W1[(size_t)k * G4 + n] = __float2half(Whh1[i]);
    }
    for (int i = gtid; i < G4 * HH; i += gstride) {          // W_ih1 -> rows 512..1023
        int r = i >> 9, k = i & 511;
        int n = ((r & 511) << 2) | (r >> 9);
        g_W1[(size_t)(HH + k) * G4 + n] = __float2half(Wih1[i]);
    }
    for (int i = gtid; i < G4; i += gstride) {
        int n = ((i & 511) << 2) | (i >> 9);
        g_bias0[n] = bih0[i] + bhh0[i];
        g_bias1[n] = bih1[i] + bhh1[i];
    }
    // zero h slot 0, reset flags (slot 0 pre-released)
    for (int i = gtid; i < BB * HH; i += gstride) {
        __half z = __float2half(0.0f);
        g_h0[i] = z; g_h1[i] = z;
    }
    for (int i = gtid; i < (TT + 1) * 4; i += gstride) {
        int v = (i < 4) ? 16 : 0;
        g_flag0[i] = v; g_flag1[i] = v;
    }
    grid_barrier();

    // ---------------- per-block tile ----------------
    const int blk = blockIdx.x;
    const bool is_l1 = (blk >= 64);
    const int tile = is_l1 ? (blk - 64) : blk;
    const int slab = tile >> 4;                  // 0..3
    const int m0 = slab * 64;
    const int n0 = (tile & 15) * 128;
    const int nch = is_l1 ? (K1 / KC) : (K0 / KC);   // 8 or 6
    const __half* W = is_l1 ? g_W1 : g_W0;
    const float* bias = is_l1 ? g_bias1 : g_bias0;
    __half* hist_out = is_l1 ? g_h1 : g_h0;
    int* flag_out = is_l1 ? g_flag1 : g_flag0;

    const int warp = tid >> 5;
    const int wm = warp >> 2;
    const int wn = warp & 3;

    float c_reg[8];
#pragma unroll
    for (int j = 0; j < 8; ++j) c_reg[j] = 0.0f;

    for (int t = 0; t < TT; ++t) {
        const __half* h0s = g_h0 + (size_t)(is_l1 ? (t + 1) : t) * BB * HH;   // l1 uses h0(t)=slot t+1; l0 uses h0(t-1)=slot t
        const __half* h1s = g_h1 + (size_t)t * BB * HH;                       // h1(t-1) = slot t
        const __half* xb = g_Xh + (size_t)t * BB * II;

        // chunk source (A): l0: [x(2) | h0prev(4)] ; l1: [h1prev(4) | h0cur(4)]
        auto Asrc = [&](int c, const __half*& s, int& ld) {
            if (!is_l1) {
                if (c < 2) { s = xb + (size_t)m0 * II + c * KC; ld = II; }
                else       { s = h0s + (size_t)m0 * HH + (c - 2) * KC; ld = HH; }
            } else {
                if (c < 4) { s = h1s + (size_t)m0 * HH + c * KC; ld = HH; }
                else       { s = h0s + (size_t)m0 * HH + (c - 4) * KC; ld = HH; }
            }
        };

        wmma::fragment<wmma::accumulator, 16, 16, 16, float> cf[2][2];
#pragma unroll
        for (int i = 0; i < 2; ++i)
#pragma unroll
            for (int j = 0; j < 2; ++j)
                wmma::fill_fragment(cf[i][j], 0.0f);

        // preload chunk 0
        if (is_l1) poll_flag(&g_flag1[t * 4 + slab]);      // h1(t-1) ready
        {
            const __half* s; int ld; Asrc(0, s, ld);
            load_chunk(smem, s, ld, W + n0);
            cp_commit();
        }

        for (int c = 0; c < nch; ++c) {
            cp_wait<0>();            // chunk c arrived (this thread's copies)
            __syncthreads();         // all copies arrived; all warps done with other stage
            if (c + 1 < nch) {
                if (!is_l1 && c + 1 == 2) poll_flag(&g_flag0[t * 4 + slab]);        // h0(t-1)
                if (is_l1 && c + 1 == 4)  poll_flag(&g_flag0[(t + 1) * 4 + slab]);  // h0(t)
                const __half* s; int ld; Asrc(c + 1, s, ld);
                load_chunk(smem + ((c + 1) & 1) * STAGE_BYTES, s, ld,
                           W + (size_t)(c + 1) * KC * G4 + n0);
                cp_commit();
            }
            // compute chunk c
            __half* sA = (__half*)(smem + (c & 1) * STAGE_BYTES);
            __half* sB = (__half*)(smem + (c & 1) * STAGE_BYTES + A_BYTES);
#pragma unroll
            for (int ks = 0; ks < KC; ks += 16) {
                wmma::fragment<wmma::matrix_a, 16, 16, 16, __half, wmma::row_major> af[2];
                wmma::fragment<wmma::matrix_b, 16, 16, 16, __half, wmma::row_major> bf[2];
#pragma unroll
                for (int i = 0; i < 2; ++i)
                    wmma::load_matrix_sync(af[i], sA + (wm * 32 + i * 16) * LDA + ks, LDA);
#pragma unroll
                for (int j = 0; j < 2; ++j)
                    wmma::load_matrix_sync(bf[j], sB + ks * LDB + wn * 32 + j * 16, LDB);
#pragma unroll
                for (int i = 0; i < 2; ++i)
#pragma unroll
                    for (int j = 0; j < 2; ++j)
                        wmma::mma_sync(cf[i][j], af[i], bf[j], cf[i][j]);
            }
        }

        // epilogue: stage0 is free (last compute used stage1; all warps passed last sync)
        float* sC = (float*)smem;
#pragma unroll
        for (int i = 0; i < 2; ++i)
#pragma unroll
            for (int j = 0; j < 2; ++j)
                wmma::store_matrix_sync(sC + (wm * 32 + i * 16) * LDC + (wn * 32 + j * 16),
                                        cf[i][j], LDC, wmma::mem_row_major);
        __syncthreads();

        __half* hout = hist_out + (size_t)(t + 1) * BB * HH;
#pragma unroll
        for (int k = 0; k < 8; ++k) {
            int idx = tid + k * NTHR;
            int r = idx >> 5;
            int j = idx & 31;
            int b = m0 + r;
            int jg = (n0 >> 2) + j;
            float4 gv = *(float4*)(sC + r * LDC + 4 * j);
            float4 bv = *(const float4*)(bias + n0 + 4 * j);
            float iv = sig_(gv.x + bv.x);
            float fv = sig_(gv.y + bv.y);
            float gg = tanh_(gv.z + bv.z);
            float ov = sig_(gv.w + bv.w);
            float cc = fv * c_reg[k] + iv * gg;
            c_reg[k] = cc;
            hout[(size_t)b * HH + jg] = __float2half(ov * tanh_(cc));
        }
        __syncthreads();             // all h stores done; sC free for next prefetch
        if (tid == 0) release_flag(&flag_out[(t + 1) * 4 + slab]);
    }

    // ---------------- head: y = h1(T-1) @ Wlin^T + b ----------------
    if (is_l1 && (tile & 15) == 0) {
        poll_flag(&g_flag1[TT * 4 + slab]);
        const __half* hfin = g_h1 + (size_t)TT * BB * HH;
        if (tid < 64) {
            int b = m0 + tid;
            float acc = blin[0];
            for (int k = 0; k < HH; k += 8) {
                uint4 v = __ldcg((const uint4*)(hfin + (size_t)b * HH + k));
                const __half* hv = (const __half*)&v;
#pragma unroll
                for (int u = 0; u < 8; ++u)
                    acc += __half2float(hv[u]) * Wlin[k + u];
            }
            out[b] = acc;
        }
    }
}

extern "C" void kernel_launch(void* const* d_in, const int* in_sizes, int n_in,
                              void* d_out, int out_size) {
    (void)in_sizes; (void)n_in; (void)out_size;
    cudaFuncSetAttribute(lstm_kernel,
                         cudaFuncAttributeMaxDynamicSharedMemorySize, SMEM_DYN);
    lstm_kernel<<<NBLK, NTHR, SMEM_DYN>>>(
        (const float*)d_in[0],
        (const float*)d_in[1], (const float*)d_in[2],
        (const float*)d_in[3], (const float*)d_in[4],
        (const float*)d_in[5], (const float*)d_in[6],
        (const float*)d_in[7], (const float*)d_in[8],
        (const float*)d_in[9], (const float*)d_in[10],
        (float*)d_out);
}

// round 7
// speedup vs baseline: 2.8068x; 1.0191x over previous
#include <cuda_runtime.h>
#include <cuda_fp16.h>
#include <mma.h>
#include <cstdint>

using namespace nvcuda;

#define BB 256
#define TT 512
#define II 256
#define HH 512
#define G4 2048
#define K0 768
#define K1 1024
#define KC 128
#define NBLK 128
#define NTHR 512
#define LDA 136            // halves (272B rows)
#define LDB 136
#define LDC 136            // floats
#define A_BYTES (64 * LDA * 2)                    // 17408
#define B_BYTES (KC * LDB * 2)                    // 34816
#define STAGE_BYTES (A_BYTES + B_BYTES)           // 52224
#define SMEM_DYN (4 * STAGE_BYTES)                // 208896

// ---------------- device global scratch ----------------
__device__ __half g_Xh[(size_t)TT * BB * II];            // [T][B][I]
__device__ __half g_W0[(size_t)K0 * G4];                 // rows [W_ih0; W_hh0], gate-interleaved cols
__device__ __half g_W1[(size_t)K1 * G4];                 // rows [W_hh1; W_ih1]
__device__ float  g_bias0[G4];
__device__ float  g_bias1[G4];
__device__ __half g_h0[(size_t)(TT + 1) * BB * HH];      // slot t+1 = output of step t
__device__ __half g_h1[(size_t)(TT + 1) * BB * HH];
__device__ int    g_flag0[(TT + 1) * 4];                 // [slot][slab], count to 16
__device__ int    g_flag1[(TT + 1) * 4];
__device__ unsigned long long g_count = 0;
__device__ volatile unsigned long long g_epoch = 0;

// ---------------- one-shot grid barrier (after prologue) ----------------
__device__ __forceinline__ void grid_barrier() {
    __syncthreads();
    if (threadIdx.x == 0) {
        __threadfence();
        unsigned long long e = g_epoch;
        if (atomicAdd(&g_count, 1ULL) == (unsigned long long)(NBLK - 1)) {
            g_count = 0;
            __threadfence();
            g_epoch = e + 1;
        } else {
            while (g_epoch == e) { __nanosleep(64); }
        }
    }
    __syncthreads();
}

__device__ __forceinline__ float sig_(float x) {
    return __fdividef(1.0f, 1.0f + __expf(-x));
}
__device__ __forceinline__ float tanh_(float x) {
    return __fmaf_rn(2.0f, sig_(2.0f * x), -1.0f);
}

// ---------------- cp.async helpers ----------------
__device__ __forceinline__ void cp_async16(void* smem, const void* g) {
    unsigned s = (unsigned)__cvta_generic_to_shared(smem);
    asm volatile("cp.async.cg.shared.global [%0], [%1], 16;" :: "r"(s), "l"(g));
}
__device__ __forceinline__ void cp_commit() { asm volatile("cp.async.commit_group;"); }
template <int N> __device__ __forceinline__ void cp_wait() {
    asm volatile("cp.async.wait_group %0;" :: "n"(N));
}
__device__ __forceinline__ void group_bar(int g) {
    asm volatile("bar.sync %0, 256;" :: "r"(g + 1) : "memory");
}

// ---------------- flag sync ----------------
__device__ __forceinline__ void poll_flag(const int* f) {
    int v = __ldcg(f);
    if (v < 16) {
        do { __nanosleep(64); v = __ldcg(f); } while (v < 16);
    }
    __threadfence();   // acquire
}
__device__ __forceinline__ void release_flag(int* f) {
    __threadfence();
    atomicAdd(f, 1);
}

// load one chunk (group-local): A 64x128 halves, B 128x128 halves
__device__ __forceinline__ void load_chunk(char* stage, int gt,
                                           const __half* __restrict__ Abase, int lda,
                                           const __half* __restrict__ Bbase)
{
    __half* sA = (__half*)stage;
    __half* sB = (__half*)(stage + A_BYTES);
#pragma unroll
    for (int i = 0; i < 4; ++i) {            // 1024 x 16B for A
        int idx = gt + i * 256;
        int r = idx >> 4, u = (idx & 15) << 3;
        cp_async16(sA + r * LDA + u, Abase + (size_t)r * lda + u);
    }
#pragma unroll
    for (int i = 0; i < 8; ++i) {            // 2048 x 16B for B
        int idx = gt + i * 256;
        int r = idx >> 4, u = (idx & 15) << 3;
        cp_async16(sB + r * LDB + u, Bbase + (size_t)r * G4 + u);
    }
}

__global__ void __launch_bounds__(NTHR, 1)
lstm_kernel(const float* __restrict__ X,
            const float* __restrict__ Wih0, const float* __restrict__ Whh0,
            const float* __restrict__ bih0, const float* __restrict__ bhh0,
            const float* __restrict__ Wih1, const float* __restrict__ Whh1,
            const float* __restrict__ bih1, const float* __restrict__ bhh1,
            const float* __restrict__ Wlin, const float* __restrict__ blin,
            float* __restrict__ out)
{
    extern __shared__ __align__(128) char smem[];

    const int tid = threadIdx.x;
    const int gtid = blockIdx.x * NTHR + tid;
    const int gstride = NBLK * NTHR;

    // ---------------- prologue ----------------
    for (int i = gtid; i < BB * TT * II; i += gstride) {
        int b = i >> 17;
        int rem = i & 131071;
        int t = rem >> 8;
        int ii = rem & 255;
        g_Xh[((size_t)t * BB + b) * II + ii] = __float2half(X[i]);
    }
    for (int i = gtid; i < G4 * II; i += gstride) {          // W_ih0 -> rows 0..255
        int r = i >> 8, k = i & 255;
        int n = ((r & 511) << 2) | (r >> 9);
        g_W0[(size_t)k * G4 + n] = __float2half(Wih0[i]);
    }
    for (int i = gtid; i < G4 * HH; i += gstride) {          // W_hh0 -> rows 256..767
        int r = i >> 9, k = i & 511;
        int n = ((r & 511) << 2) | (r >> 9);
        g_W0[(size_t)(II + k) * G4 + n] = __float2half(Whh0[i]);
    }
    for (int i = gtid; i < G4 * HH; i += gstride) {          // W_hh1 -> rows 0..511
        int r = i >> 9, k = i & 511;
        int n = ((r & 511) << 2) | (r >> 9);
        g_W1[(size_t)k * G4 + n] = __float2half(Whh1[i]);
    }
    for (int i = gtid; i < G4 * HH; i += gstride) {          // W_ih1 -> rows 512..1023
        int r = i >> 9, k = i & 511;
        int n = ((r & 511) << 2) | (r >> 9);
        g_W1[(size_t)(HH + k) * G4 + n] = __float2half(Wih1[i]);
    }
    for (int i = gtid; i < G4; i += gstride) {
        int n = ((i & 511) << 2) | (i >> 9);
        g_bias0[n] = bih0[i] + bhh0[i];
        g_bias1[n] = bih1[i] + bhh1[i];
    }
    for (int i = gtid; i < BB * HH; i += gstride) {
        __half z = __float2half(0.0f);
        g_h0[i] = z; g_h1[i] = z;
    }
    for (int i = gtid; i < (TT + 1) * 4; i += gstride) {
        int v = (i < 4) ? 16 : 0;
        g_flag0[i] = v; g_flag1[i] = v;
    }
    grid_barrier();

    // ---------------- per-block tile ----------------
    const int blk = blockIdx.x;
    const bool is_l1 = (blk >= 64);
    const int tile = is_l1 ? (blk - 64) : blk;
    const int slab = tile >> 4;                  // 0..3
    const int m0 = slab * 64;
    const int n0 = (tile & 15) * 128;
    const int nch = is_l1 ? (K1 / KC) : (K0 / KC);   // 8 or 6
    const int nch2 = nch >> 1;                       // per-group chunks
    const __half* W = is_l1 ? g_W1 : g_W0;
    const float* bias = is_l1 ? g_bias1 : g_bias0;
    __half* hist_out = is_l1 ? g_h1 : g_h0;
    int* flag_out = is_l1 ? g_flag1 : g_flag0;

    const int warp = tid >> 5;
    const int g = warp >> 3;                     // warp-group 0/1
    const int gwarp = warp & 7;
    const int gt = tid & 255;
    const int wm = gwarp >> 2;
    const int wn = gwarp & 3;
    char* gstage0 = smem + (g * 2) * STAGE_BYTES;        // group's stage pair
    char* gstage1 = smem + (g * 2 + 1) * STAGE_BYTES;
    float* sC0 = (float*)smem;                            // aliases stage0
    float* sC1 = (float*)(smem + 2 * STAGE_BYTES);        // aliases stage2
    float* sCg = g ? sC1 : sC0;

    float c_reg[4];
#pragma unroll
    for (int j = 0; j < 4; ++j) c_reg[j] = 0.0f;

    for (int t = 0; t < TT; ++t) {
        const __half* h0s = g_h0 + (size_t)(is_l1 ? (t + 1) : t) * BB * HH;
        const __half* h1s = g_h1 + (size_t)t * BB * HH;
        const __half* xb = g_Xh + (size_t)t * BB * II;

        // chunk source (A): l0: [x(2) | h0prev(4)] ; l1: [h1prev(4) | h0cur(4)]
        auto Asrc = [&](int c, const __half*& s, int& ld) {
            if (!is_l1) {
                if (c < 2) { s = xb + (size_t)m0 * II + c * KC; ld = II; }
                else       { s = h0s + (size_t)m0 * HH + (c - 2) * KC; ld = HH; }
            } else {
                if (c < 4) { s = h1s + (size_t)m0 * HH + c * KC; ld = HH; }
                else       { s = h0s + (size_t)m0 * HH + (c - 4) * KC; ld = HH; }
            }
        };

        wmma::fragment<wmma::accumulator, 16, 16, 16, float> cf[2][2];
#pragma unroll
        for (int i = 0; i < 2; ++i)
#pragma unroll
            for (int j = 0; j < 2; ++j)
                wmma::fill_fragment(cf[i][j], 0.0f);

        // preload this group's chunk 0 (c = g)
        if (is_l1) poll_flag(&g_flag1[t * 4 + slab]);      // h1(t-1) ready
        {
            const __half* s; int ld; Asrc(g, s, ld);
            load_chunk(gstage0, gt, s, ld, W + (size_t)g * KC * G4 + n0);
            cp_commit();
        }

        for (int l = 0; l < nch2; ++l) {
            const int c = 2 * l + g;
            cp_wait<0>();            // this thread's copies for chunk c done
            group_bar(g);            // whole group's copies done; prev stage free
            if (l + 1 < nch2) {
                const int cn = c + 2;
                if (!is_l1 && l + 1 == 1) poll_flag(&g_flag0[t * 4 + slab]);        // h0(t-1)
                if (is_l1 && l + 1 == 2)  poll_flag(&g_flag0[(t + 1) * 4 + slab]);  // h0(t)
                const __half* s; int ld; Asrc(cn, s, ld);
                load_chunk(((l + 1) & 1) ? gstage1 : gstage0, gt, s, ld,
                           W + (size_t)cn * KC * G4 + n0);
                cp_commit();
            }
            // compute chunk c
            char* st = (l & 1) ? gstage1 : gstage0;
            __half* sA = (__half*)st;
            __half* sB = (__half*)(st + A_BYTES);
#pragma unroll
            for (int ks = 0; ks < KC; ks += 16) {
                wmma::fragment<wmma::matrix_a, 16, 16, 16, __half, wmma::row_major> af[2];
                wmma::fragment<wmma::matrix_b, 16, 16, 16, __half, wmma::row_major> bf[2];
#pragma unroll
                for (int i = 0; i < 2; ++i)
                    wmma::load_matrix_sync(af[i], sA + (wm * 32 + i * 16) * LDA + ks, LDA);
#pragma unroll
                for (int j = 0; j < 2; ++j)
                    wmma::load_matrix_sync(bf[j], sB + ks * LDB + wn * 32 + j * 16, LDB);
#pragma unroll
                for (int i = 0; i < 2; ++i)
#pragma unroll
                    for (int j = 0; j < 2; ++j)
                        wmma::mma_sync(cf[i][j], af[i], bf[j], cf[i][j]);
            }
        }

        // all group warps done computing -> safe to overwrite group's stage0 with partials
        group_bar(g);
#pragma unroll
        for (int i = 0; i < 2; ++i)
#pragma unroll
            for (int j = 0; j < 2; ++j)
                wmma::store_matrix_sync(sCg + (wm * 32 + i * 16) * LDC + (wn * 32 + j * 16),
                                        cf[i][j], LDC, wmma::mem_row_major);
        __syncthreads();

        // fused LSTM cell: sum the two split-K partials, cols 4j.. = (i,f,g,o)
        __half* hout = hist_out + (size_t)(t + 1) * BB * HH;
#pragma unroll
        for (int k = 0; k < 4; ++k) {
            int idx = tid + k * NTHR;
            int r = idx >> 5;
            int j = idx & 31;
            int b = m0 + r;
            int jg = (n0 >> 2) + j;
            float4 g0 = *(float4*)(sC0 + r * LDC + 4 * j);
            float4 g1 = *(float4*)(sC1 + r * LDC + 4 * j);
            float4 bv = *(const float4*)(bias + n0 + 4 * j);
            float iv = sig_(g0.x + g1.x + bv.x);
            float fv = sig_(g0.y + g1.y + bv.y);
            float gg = tanh_(g0.z + g1.z + bv.z);
            float ov = sig_(g0.w + g1.w + bv.w);
            float cc = fv * c_reg[k] + iv * gg;
            c_reg[k] = cc;
            hout[(size_t)b * HH + jg] = __float2half(ov * tanh_(cc));
        }
        __syncthreads();             // h stores + sC reads done; stages reusable
        if (tid == 0) release_flag(&flag_out[(t + 1) * 4 + slab]);
    }

    // ---------------- head: y = h1(T-1) @ Wlin^T + b ----------------
    if (is_l1 && (tile & 15) == 0) {
        poll_flag(&g_flag1[TT * 4 + slab]);
        const __half* hfin = g_h1 + (size_t)TT * BB * HH;
        if (tid < 64) {
            int b = m0 + tid;
            float acc = blin[0];
            for (int k = 0; k < HH; k += 8) {
                uint4 v = __ldcg((const uint4*)(hfin + (size_t)b * HH + k));
                const __half* hv = (const __half*)&v;
#pragma unroll
                for (int u = 0; u < 8; ++u)
                    acc += __half2float(hv[u]) * Wlin[k + u];
            }
            out[b] = acc;
        }
    }
}

extern "C" void kernel_launch(void* const* d_in, const int* in_sizes, int n_in,
                              void* d_out, int out_size) {
    (void)in_sizes; (void)n_in; (void)out_size;
    cudaFuncSetAttribute(lstm_kernel,
                         cudaFuncAttributeMaxDynamicSharedMemorySize, SMEM_DYN);
    lstm_kernel<<<NBLK, NTHR, SMEM_DYN>>>(
        (const float*)d_in[0],
        (const float*)d_in[1], (const float*)d_in[2],
        (const float*)d_in[3], (const float*)d_in[4],
        (const float*)d_in[5], (const float*)d_in[6],
        (const float*)d_in[7], (const float*)d_in[8],
        (const float*)d_in[9], (const float*)d_in[10],
        (float*)d_out);
}